// round 12
// baseline (speedup 1.0000x reference)
#include <cuda_runtime.h>
#include <math.h>

#define MAXN 100000
#define MAXE 1200000
#define SCAN_B 512
#define MAXBLK 256

// ---- scratch (static __device__, allocation-free; zero-initialized at load) ----
__device__ __align__(16) float g_h[(size_t)MAXN * 64];   // h = x@W (row stride = Do)
__device__ float               g_as[MAXN];               // h @ a_src
__device__ float               g_ad[MAXN];               // h @ a_dst
__device__ __align__(16) float g_x[(size_t)MAXN * 64];   // layer output -> next input
__device__ int                 g_deg[MAXN];              // in-degree (ZERO at call entry)
__device__ int                 g_rowptr[MAXN];           // after scatter: rowptr[n] = end(n)
__device__ int                 g_csrc[MAXE];             // CSR src indices (grouped by dst)
// decoupled-lookback scan state (ZERO flags at call entry)
__device__ volatile int        g_flag[MAXBLK];
__device__ volatile int        g_aggr[MAXBLK];
__device__ volatile int        g_incl[MAXBLK];

__device__ __forceinline__ float lrelu(float x) { return x > 0.f ? x : 0.2f * x; }

// ================= CSR build: 3 kernels =================

__global__ void hist_k(const int* __restrict__ ei, int E) {
    int i4 = blockIdx.x * blockDim.x + threadIdx.x;
    const int* dst = ei + E;
    int base = i4 * 4;
    if (base + 3 < E) {
        int4 d = *(const int4*)(dst + base);
        atomicAdd(&g_deg[d.x], 1);
        atomicAdd(&g_deg[d.y], 1);
        atomicAdd(&g_deg[d.z], 1);
        atomicAdd(&g_deg[d.w], 1);
    } else {
        for (int i = base; i < E; i++) atomicAdd(&g_deg[dst[i]], 1);
    }
}

// single-pass exclusive scan (decoupled lookback); g_flag zero at entry
__global__ void scan_k(int N) {
    __shared__ int wsum[16];
    __shared__ int s_off;
    int tid = threadIdx.x, b = blockIdx.x;
    int lane = tid & 31, wid = tid >> 5;
    int i = b * SCAN_B + tid;
    int v = (i < N) ? g_deg[i] : 0;

    int x = v;
#pragma unroll
    for (int o = 1; o < 32; o <<= 1) {
        int t = __shfl_up_sync(0xffffffffu, x, o);
        if (lane >= o) x += t;
    }
    if (lane == 31) wsum[wid] = x;
    __syncthreads();
    if (wid == 0 && lane < 16) {
        int y = wsum[lane];
#pragma unroll
        for (int o = 1; o < 16; o <<= 1) {
            int t = __shfl_up_sync(0x0000ffffu, y, o);
            if (lane >= o) y += t;
        }
        wsum[lane] = y;
    }
    __syncthreads();
    int incl  = x + (wid > 0 ? wsum[wid - 1] : 0);
    int total = wsum[15];

    if (tid == 0) {
        if (b == 0) {
            g_incl[0] = total;
            __threadfence();
            g_flag[0] = 2;
            s_off = 0;
        } else {
            g_aggr[b] = total;
            __threadfence();
            g_flag[b] = 1;
            int run = 0;
            for (int p = b - 1; p >= 0; p--) {
                int f;
                do { f = g_flag[p]; } while (f == 0);
                if (f == 2) { run += g_incl[p]; break; }
                run += g_aggr[p];
            }
            s_off = run;
            g_incl[b] = run + total;
            __threadfence();
            g_flag[b] = 2;
        }
    }
    __syncthreads();
    if (i < N) g_rowptr[i] = s_off + incl - v;     // exclusive
}

__global__ void scatter_k(const int* __restrict__ ei, int E) {
    int i4 = blockIdx.x * blockDim.x + threadIdx.x;
    int base = i4 * 4;
    if (base + 3 < E) {
        int4 s = *(const int4*)(ei + base);
        int4 d = *(const int4*)(ei + E + base);
        g_csrc[atomicAdd(&g_rowptr[d.x], 1)] = s.x;
        g_csrc[atomicAdd(&g_rowptr[d.y], 1)] = s.y;
        g_csrc[atomicAdd(&g_rowptr[d.z], 1)] = s.z;
        g_csrc[atomicAdd(&g_rowptr[d.w], 1)] = s.w;
    } else {
        for (int i = base; i < E; i++)
            g_csrc[atomicAdd(&g_rowptr[ei[E + i]], 1)] = ei[i];
    }
}

// restore zeroed-state invariant for the next call (runs LAST)
__global__ void cleanup(int N) {
    int i = blockIdx.x * blockDim.x + threadIdx.x;
    if (i < N) g_deg[i] = 0;
    if (i < MAXBLK) g_flag[i] = 0;
}

// ================= K1: register-tiled GEMM + attention scores =================
// 128x64 output tile, 256 threads, 8x4 per thread (scalar FFMA, ~60 regs).
// As[k][r] swizzled transpose (XOR on 16B row-groups); Bs[k][c] zero-padded.
// Per k per thread: 2x broadcast LDS.128 (a) + 1x LDS.128 (b) + 32 FFMA -> 4:1.
template <int Do, bool FROMG>
__global__ void __launch_bounds__(256) gemm_attn(
        const float* __restrict__ xin, const float* __restrict__ W,
        const float* __restrict__ a_s, const float* __restrict__ a_d, int N) {
    const int Din = 64;
    __shared__ float As[Din * 128];    // 32KB, swizzled [k][r]
    __shared__ float Bs[Din * 64];     // 16KB  [k][c]

    int t  = threadIdx.x;              // 0..255
    int tx = t & 15;                   // col group (4 cols each)
    int ty = t >> 4;                   // row group (8 rows each, 0..15)
    int rowbase = blockIdx.x * 128;

    const float* src = FROMG ? g_x : xin;

    // fill As: transpose x into [k][r], group-swizzled (rg ^= k&31)
    {
        int kg = (t & 15) * 4;         // base k of this thread's float4
        int r0 = t >> 4;               // 0..15
#pragma unroll
        for (int q = 0; q < 8; q++) {
            int r = r0 + q * 16;
            int row = rowbase + r;
            float4 x4 = (row < N) ? *(const float4*)(src + (size_t)row * Din + kg)
                                  : make_float4(0.f, 0.f, 0.f, 0.f);
            int rg = r >> 2, rl = r & 3;
            As[(kg + 0) * 128 + ((rg ^ ((kg + 0) & 31)) << 2) + rl] = x4.x;
            As[(kg + 1) * 128 + ((rg ^ ((kg + 1) & 31)) << 2) + rl] = x4.y;
            As[(kg + 2) * 128 + ((rg ^ ((kg + 2) & 31)) << 2) + rl] = x4.z;
            As[(kg + 3) * 128 + ((rg ^ ((kg + 3) & 31)) << 2) + rl] = x4.w;
        }
    }
    // fill Bs
    {
        int c4 = (t & 15) * 4;
        int k0 = t >> 4;
#pragma unroll
        for (int q = 0; q < 4; q++) {
            int k = k0 + q * 16;
            float4 w4 = (c4 < Do) ? *(const float4*)(W + (size_t)k * Do + c4)
                                  : make_float4(0.f, 0.f, 0.f, 0.f);
            *(float4*)&Bs[k * 64 + c4] = w4;
        }
    }
    __syncthreads();

    float acc[8][4] = {};
#pragma unroll 8
    for (int k = 0; k < Din; k++) {
        int sw = k & 31;
        const float* arow = &As[k * 128];
        float4 a0 = *(const float4*)(arow + ((((ty * 2)     ^ sw) << 2)));  // rows ty*8..+3
        float4 a1 = *(const float4*)(arow + ((((ty * 2 + 1) ^ sw) << 2)));  // rows ty*8+4..+7
        float4 bb = *(const float4*)&Bs[k * 64 + tx * 4];
        acc[0][0] += a0.x * bb.x; acc[0][1] += a0.x * bb.y; acc[0][2] += a0.x * bb.z; acc[0][3] += a0.x * bb.w;
        acc[1][0] += a0.y * bb.x; acc[1][1] += a0.y * bb.y; acc[1][2] += a0.y * bb.z; acc[1][3] += a0.y * bb.w;
        acc[2][0] += a0.z * bb.x; acc[2][1] += a0.z * bb.y; acc[2][2] += a0.z * bb.z; acc[2][3] += a0.z * bb.w;
        acc[3][0] += a0.w * bb.x; acc[3][1] += a0.w * bb.y; acc[3][2] += a0.w * bb.z; acc[3][3] += a0.w * bb.w;
        acc[4][0] += a1.x * bb.x; acc[4][1] += a1.x * bb.y; acc[4][2] += a1.x * bb.z; acc[4][3] += a1.x * bb.w;
        acc[5][0] += a1.y * bb.x; acc[5][1] += a1.y * bb.y; acc[5][2] += a1.y * bb.z; acc[5][3] += a1.y * bb.w;
        acc[6][0] += a1.z * bb.x; acc[6][1] += a1.z * bb.y; acc[6][2] += a1.z * bb.z; acc[6][3] += a1.z * bb.w;
        acc[7][0] += a1.w * bb.x; acc[7][1] += a1.w * bb.y; acc[7][2] += a1.w * bb.z; acc[7][3] += a1.w * bb.w;
    }

    int c4 = tx * 4;
    float4 av = (c4 < Do) ? *(const float4*)(a_s + c4) : make_float4(0.f, 0.f, 0.f, 0.f);
    float4 dv = (c4 < Do) ? *(const float4*)(a_d + c4) : make_float4(0.f, 0.f, 0.f, 0.f);

#pragma unroll
    for (int i = 0; i < 8; i++) {
        int row = rowbase + ty * 8 + i;
        float ps = acc[i][0] * av.x + acc[i][1] * av.y + acc[i][2] * av.z + acc[i][3] * av.w;
        float pd = acc[i][0] * dv.x + acc[i][1] * dv.y + acc[i][2] * dv.z + acc[i][3] * dv.w;
        // reduce across the 16 tx-lanes sharing this row (stays within half-warp)
#pragma unroll
        for (int o = 8; o > 0; o >>= 1) {
            ps += __shfl_xor_sync(0xffffffffu, ps, o);
            pd += __shfl_xor_sync(0xffffffffu, pd, o);
        }
        if (row < N) {
            if (c4 < Do)
                *(float4*)(g_h + (size_t)row * Do + c4) =
                    make_float4(acc[i][0], acc[i][1], acc[i][2], acc[i][3]);
            if (tx == 0) { g_as[row] = ps; g_ad[row] = pd; }
        }
    }
}

// ================= K2: softmax + aggregate (warp per node, float2 lanes) =====
// Shift by self-score (softmax shift-invariant; scores O(10), fp32-safe).
// MODE 0: relu(acc/den + b) -> g_x (Do=64, GOUT=true); MODE 1: log_softmax -> out.
template <int Do, int MODE, bool GOUT>
__global__ void agg(const float* __restrict__ b, float* __restrict__ out_arg, int N) {
    const unsigned FULL = 0xffffffffu;
    float* out = GOUT ? g_x : out_arg;
    int w    = (blockIdx.x * blockDim.x + threadIdx.x) >> 5;
    int lane = threadIdx.x & 31;
    if (w >= N) return;
    const int n = w;

    int end   = g_rowptr[n];
    int start = end - g_deg[n];
    float ad_n  = g_ad[n];
    float eself = lrelu(g_as[n] + ad_n);

    const int HL = Do / 2;
    bool act = (lane < HL);
    float2 acc = act ? *(const float2*)(g_h + (size_t)n * Do + 2 * lane)
                     : make_float2(0.f, 0.f);            // self contribution (ex=1)
    float den_p = (lane == 0) ? 1.f : 0.f;

    for (int base = start; base < end; base += 32) {
        int i = base + lane;
        int   s = 0;
        float ex = 0.f;
        if (i < end) {
            s  = g_csrc[i];
            ex = __expf(lrelu(g_as[s] + ad_n) - eself);
        }
        den_p += ex;

        int cnt = min(32, end - base);
        int j = 0;
        for (; j + 4 <= cnt; j += 4) {
            int   s0 = __shfl_sync(FULL, s, j),     s1 = __shfl_sync(FULL, s, j + 1);
            int   s2 = __shfl_sync(FULL, s, j + 2), s3 = __shfl_sync(FULL, s, j + 3);
            float e0 = __shfl_sync(FULL, ex, j),     e1 = __shfl_sync(FULL, ex, j + 1);
            float e2 = __shfl_sync(FULL, ex, j + 2), e3 = __shfl_sync(FULL, ex, j + 3);
            if (act) {
                float2 h0 = *(const float2*)(g_h + (size_t)s0 * Do + 2 * lane);
                float2 h1 = *(const float2*)(g_h + (size_t)s1 * Do + 2 * lane);
                float2 h2 = *(const float2*)(g_h + (size_t)s2 * Do + 2 * lane);
                float2 h3 = *(const float2*)(g_h + (size_t)s3 * Do + 2 * lane);
                acc.x += e0 * h0.x; acc.y += e0 * h0.y;
                acc.x += e1 * h1.x; acc.y += e1 * h1.y;
                acc.x += e2 * h2.x; acc.y += e2 * h2.y;
                acc.x += e3 * h3.x; acc.y += e3 * h3.y;
            }
        }
        for (; j < cnt; j++) {
            int   sj = __shfl_sync(FULL, s, j);
            float ej = __shfl_sync(FULL, ex, j);
            if (act) {
                float2 hj = *(const float2*)(g_h + (size_t)sj * Do + 2 * lane);
                acc.x += ej * hj.x; acc.y += ej * hj.y;
            }
        }
    }
#pragma unroll
    for (int o = 16; o > 0; o >>= 1)
        den_p += __shfl_xor_sync(FULL, den_p, o);
    float inv = 1.f / den_p;

    if (MODE == 0) {
        float2 bv = *(const float2*)(b + 2 * lane);
        float2 o2;
        o2.x = fmaxf(acc.x * inv + bv.x, 0.f);
        o2.y = fmaxf(acc.y * inv + bv.y, 0.f);
        *(float2*)(out + (size_t)n * 64 + 2 * lane) = o2;
    } else {
        float v0 = act ? (acc.x * inv + b[2 * lane])     : -INFINITY;
        float v1 = act ? (acc.y * inv + b[2 * lane + 1]) : -INFINITY;
        float mx = fmaxf(v0, v1);
#pragma unroll
        for (int o = 16; o > 0; o >>= 1)
            mx = fmaxf(mx, __shfl_xor_sync(FULL, mx, o));
        float sum = act ? (expf(v0 - mx) + expf(v1 - mx)) : 0.f;
#pragma unroll
        for (int o = 16; o > 0; o >>= 1)
            sum += __shfl_xor_sync(FULL, sum, o);
        float ls = mx + logf(sum);
        if (act) {
            out[(size_t)n * 40 + 2 * lane]     = v0 - ls;
            out[(size_t)n * 40 + 2 * lane + 1] = v1 - ls;
        }
    }
}

extern "C" void kernel_launch(void* const* d_in, const int* in_sizes, int n_in,
                              void* d_out, int out_size) {
    const int N = in_sizes[0] / 64;
    const int E = in_sizes[1] / 2;
    const float* x  = (const float*)d_in[0];
    const int*   ei = (const int*)d_in[1];     // int32 (JAX downcasts int64)

    const int TB = 256;
    int nblk  = (N + TB - 1) / TB;
    int e4blk = ((E + 3) / 4 + TB - 1) / TB;
    int sblk  = (N + SCAN_B - 1) / SCAN_B;
    int gemm_grid = (N + 127) / 128;
    int agg_grid  = (N + 7) / 8;

    // ---- CSR build ----
    hist_k<<<e4blk, TB>>>(ei, E);
    scan_k<<<sblk, SCAN_B>>>(N);
    scatter_k<<<e4blk, TB>>>(ei, E);

    // ---------- layer 0 ----------
    gemm_attn<64, false><<<gemm_grid, TB>>>(x, (const float*)d_in[2],
                                            (const float*)d_in[3], (const float*)d_in[4], N);
    agg<64, 0, true><<<agg_grid, TB>>>((const float*)d_in[5], nullptr, N);

    // ---------- layer 1 ----------
    gemm_attn<64, true><<<gemm_grid, TB>>>(nullptr, (const float*)d_in[6],
                                           (const float*)d_in[7], (const float*)d_in[8], N);
    agg<64, 0, true><<<agg_grid, TB>>>((const float*)d_in[9], nullptr, N);

    // ---------- layer 2 ----------
    gemm_attn<40, true><<<gemm_grid, TB>>>(nullptr, (const float*)d_in[10],
                                           (const float*)d_in[11], (const float*)d_in[12], N);
    agg<40, 1, false><<<agg_grid, TB>>>((const float*)d_in[13], (float*)d_out, N);

    // ---- restore zeroed-state invariant for next call ----
    cleanup<<<nblk, TB>>>(N);
}

// round 13
// speedup vs baseline: 1.0068x; 1.0068x over previous
#include <cuda_runtime.h>
#include <math.h>

#define MAXN 100000
#define MAXE 1200000
#define SCAN_B 512
#define MAXBLK 256

// ---- scratch (static __device__, allocation-free; zero-initialized at load) ----
__device__ __align__(16) float g_h[(size_t)MAXN * 64];   // h = x@W (row stride = Do)
__device__ float               g_as[MAXN];               // h @ a_src
__device__ float               g_ad[MAXN];               // h @ a_dst
__device__ __align__(16) float g_x[(size_t)MAXN * 64];   // layer output -> next input
__device__ int                 g_deg[MAXN];              // in-degree (ZERO at call entry)
__device__ int                 g_rowstart[MAXN];         // CSR row start (exclusive scan)
__device__ int                 g_rowptr[MAXN];           // after scatter: rowptr[n] = end(n)
__device__ int                 g_csrc[MAXE];             // CSR src indices (grouped by dst)
// decoupled-lookback scan state (ZERO flags at call entry)
__device__ volatile int        g_flag[MAXBLK];
__device__ volatile int        g_aggr[MAXBLK];
__device__ volatile int        g_incl[MAXBLK];

__device__ __forceinline__ float lrelu(float x) { return x > 0.f ? x : 0.2f * x; }

// ================= CSR build: 3 kernels =================

__global__ void hist_k(const int* __restrict__ ei, int E) {
    int i4 = blockIdx.x * blockDim.x + threadIdx.x;
    const int* dst = ei + E;
    int base = i4 * 4;
    if (base + 3 < E) {
        int4 d = *(const int4*)(dst + base);
        atomicAdd(&g_deg[d.x], 1);
        atomicAdd(&g_deg[d.y], 1);
        atomicAdd(&g_deg[d.z], 1);
        atomicAdd(&g_deg[d.w], 1);
    } else {
        for (int i = base; i < E; i++) atomicAdd(&g_deg[dst[i]], 1);
    }
}

// single-pass exclusive scan (decoupled lookback); g_flag zero at entry.
// Writes BOTH g_rowstart (persistent) and g_rowptr (advanced by scatter).
__global__ void scan_k(int N) {
    __shared__ int wsum[16];
    __shared__ int s_off;
    int tid = threadIdx.x, b = blockIdx.x;
    int lane = tid & 31, wid = tid >> 5;
    int i = b * SCAN_B + tid;
    int v = (i < N) ? g_deg[i] : 0;

    int x = v;
#pragma unroll
    for (int o = 1; o < 32; o <<= 1) {
        int t = __shfl_up_sync(0xffffffffu, x, o);
        if (lane >= o) x += t;
    }
    if (lane == 31) wsum[wid] = x;
    __syncthreads();
    if (wid == 0 && lane < 16) {
        int y = wsum[lane];
#pragma unroll
        for (int o = 1; o < 16; o <<= 1) {
            int t = __shfl_up_sync(0x0000ffffu, y, o);
            if (lane >= o) y += t;
        }
        wsum[lane] = y;
    }
    __syncthreads();
    int incl  = x + (wid > 0 ? wsum[wid - 1] : 0);
    int total = wsum[15];

    if (tid == 0) {
        if (b == 0) {
            g_incl[0] = total;
            __threadfence();
            g_flag[0] = 2;
            s_off = 0;
        } else {
            g_aggr[b] = total;
            __threadfence();
            g_flag[b] = 1;
            int run = 0;
            for (int p = b - 1; p >= 0; p--) {
                int f;
                do { f = g_flag[p]; } while (f == 0);
                if (f == 2) { run += g_incl[p]; break; }
                run += g_aggr[p];
            }
            s_off = run;
            g_incl[b] = run + total;
            __threadfence();
            g_flag[b] = 2;
        }
    }
    __syncthreads();
    if (i < N) {
        int excl = s_off + incl - v;
        g_rowstart[i] = excl;
        g_rowptr[i]   = excl;
    }
}

// scatter edges into CSR slots; ALSO restores the zeroed-state invariant for
// g_deg / g_flag (this kernel runs after scan_k, their last consumer).
__global__ void scatter_k(const int* __restrict__ ei, int E, int N) {
    int id = blockIdx.x * blockDim.x + threadIdx.x;
    int base = id * 4;
    if (base + 3 < E) {
        int4 s = *(const int4*)(ei + base);
        int4 d = *(const int4*)(ei + E + base);
        g_csrc[atomicAdd(&g_rowptr[d.x], 1)] = s.x;
        g_csrc[atomicAdd(&g_rowptr[d.y], 1)] = s.y;
        g_csrc[atomicAdd(&g_rowptr[d.z], 1)] = s.z;
        g_csrc[atomicAdd(&g_rowptr[d.w], 1)] = s.w;
    } else {
        for (int i = base; i < E; i++)
            g_csrc[atomicAdd(&g_rowptr[ei[E + i]], 1)] = ei[i];
    }
    if (id < N) g_deg[id] = 0;
    if (id < MAXBLK) g_flag[id] = 0;
}

// ================= K1: register-tiled GEMM + attention scores =================
// (R10 config — measured best.) 64x64 tile, 256 threads, 4x4 per thread.
// As[k][row] stride 68 (16B-aligned rows + bank rotation); Bs[k][col].
template <int Do, bool FROMG>
__global__ void gemm_attn(const float* __restrict__ xin, const float* __restrict__ W,
                          const float* __restrict__ a_s, const float* __restrict__ a_d,
                          int N) {
    const int Din = 64;
    __shared__ float As[Din][68];
    __shared__ float Bs[Din][64];

    int t  = threadIdx.x;
    int tx = t & 15;
    int ty = t >> 4;
    int rowbase = blockIdx.x * 64;

    const float* src = FROMG ? g_x : xin;

    {
        int r0 = t >> 4;
        int k4 = (t & 15) * 4;
#pragma unroll
        for (int q = 0; q < 4; q++) {
            int r = r0 + q * 16;
            int row = rowbase + r;
            float4 x4 = (row < N) ? *(const float4*)(src + (size_t)row * Din + k4)
                                  : make_float4(0.f, 0.f, 0.f, 0.f);
            As[k4 + 0][r] = x4.x;
            As[k4 + 1][r] = x4.y;
            As[k4 + 2][r] = x4.z;
            As[k4 + 3][r] = x4.w;
        }
    }
    {
        int kk = t >> 4;
        int c4 = (t & 15) * 4;
#pragma unroll
        for (int q = 0; q < 4; q++) {
            int k = kk + q * 16;
            float4 w4 = (c4 < Do) ? *(const float4*)(W + (size_t)k * Do + c4)
                                  : make_float4(0.f, 0.f, 0.f, 0.f);
            *(float4*)&Bs[k][c4] = w4;
        }
    }
    __syncthreads();

    float acc[4][4] = {};
#pragma unroll 8
    for (int k = 0; k < Din; k++) {
        float4 a  = *(const float4*)&As[k][ty * 4];
        float4 bb = *(const float4*)&Bs[k][tx * 4];
        acc[0][0] += a.x * bb.x; acc[0][1] += a.x * bb.y; acc[0][2] += a.x * bb.z; acc[0][3] += a.x * bb.w;
        acc[1][0] += a.y * bb.x; acc[1][1] += a.y * bb.y; acc[1][2] += a.y * bb.z; acc[1][3] += a.y * bb.w;
        acc[2][0] += a.z * bb.x; acc[2][1] += a.z * bb.y; acc[2][2] += a.z * bb.z; acc[2][3] += a.z * bb.w;
        acc[3][0] += a.w * bb.x; acc[3][1] += a.w * bb.y; acc[3][2] += a.w * bb.z; acc[3][3] += a.w * bb.w;
    }

    int c4 = tx * 4;
    float4 av = (c4 < Do) ? *(const float4*)(a_s + c4) : make_float4(0.f, 0.f, 0.f, 0.f);
    float4 dv = (c4 < Do) ? *(const float4*)(a_d + c4) : make_float4(0.f, 0.f, 0.f, 0.f);

#pragma unroll
    for (int i = 0; i < 4; i++) {
        int row = rowbase + ty * 4 + i;
        float ps = acc[i][0] * av.x + acc[i][1] * av.y + acc[i][2] * av.z + acc[i][3] * av.w;
        float pd = acc[i][0] * dv.x + acc[i][1] * dv.y + acc[i][2] * dv.z + acc[i][3] * dv.w;
#pragma unroll
        for (int o = 8; o > 0; o >>= 1) {
            ps += __shfl_xor_sync(0xffffffffu, ps, o);
            pd += __shfl_xor_sync(0xffffffffu, pd, o);
        }
        if (row < N) {
            if (c4 < Do)
                *(float4*)(g_h + (size_t)row * Do + c4) =
                    make_float4(acc[i][0], acc[i][1], acc[i][2], acc[i][3]);
            if (tx == 0) { g_as[row] = ps; g_ad[row] = pd; }
        }
    }
}

// ================= K2: softmax + aggregate (warp per node, float2 lanes) =====
// Shift by self-score (softmax shift-invariant; scores O(10), fp32-safe).
// MODE 0: relu(acc/den + b) -> g_x (Do=64, GOUT=true); MODE 1: log_softmax -> out.
template <int Do, int MODE, bool GOUT>
__global__ void agg(const float* __restrict__ b, float* __restrict__ out_arg, int N) {
    const unsigned FULL = 0xffffffffu;
    float* out = GOUT ? g_x : out_arg;
    int w    = (blockIdx.x * blockDim.x + threadIdx.x) >> 5;
    int lane = threadIdx.x & 31;
    if (w >= N) return;
    const int n = w;

    int start = g_rowstart[n];
    int end   = g_rowptr[n];
    float ad_n  = g_ad[n];
    float eself = lrelu(g_as[n] + ad_n);

    const int HL = Do / 2;
    bool act = (lane < HL);
    float2 acc = act ? *(const float2*)(g_h + (size_t)n * Do + 2 * lane)
                     : make_float2(0.f, 0.f);            // self contribution (ex=1)
    float den_p = (lane == 0) ? 1.f : 0.f;

    for (int base = start; base < end; base += 32) {
        int i = base + lane;
        int   s = 0;
        float ex = 0.f;
        if (i < end) {
            s  = g_csrc[i];
            ex = __expf(lrelu(g_as[s] + ad_n) - eself);
        }
        den_p += ex;

        int cnt = min(32, end - base);
        int j = 0;
        for (; j + 8 <= cnt; j += 8) {
#pragma unroll
            for (int u = 0; u < 8; u += 4) {
                int   s0 = __shfl_sync(FULL, s, j + u),     s1 = __shfl_sync(FULL, s, j + u + 1);
                int   s2 = __shfl_sync(FULL, s, j + u + 2), s3 = __shfl_sync(FULL, s, j + u + 3);
                float e0 = __shfl_sync(FULL, ex, j + u),     e1 = __shfl_sync(FULL, ex, j + u + 1);
                float e2 = __shfl_sync(FULL, ex, j + u + 2), e3 = __shfl_sync(FULL, ex, j + u + 3);
                if (act) {
                    float2 h0 = *(const float2*)(g_h + (size_t)s0 * Do + 2 * lane);
                    float2 h1 = *(const float2*)(g_h + (size_t)s1 * Do + 2 * lane);
                    float2 h2 = *(const float2*)(g_h + (size_t)s2 * Do + 2 * lane);
                    float2 h3 = *(const float2*)(g_h + (size_t)s3 * Do + 2 * lane);
                    acc.x += e0 * h0.x; acc.y += e0 * h0.y;
                    acc.x += e1 * h1.x; acc.y += e1 * h1.y;
                    acc.x += e2 * h2.x; acc.y += e2 * h2.y;
                    acc.x += e3 * h3.x; acc.y += e3 * h3.y;
                }
            }
        }
        for (; j < cnt; j++) {
            int   sj = __shfl_sync(FULL, s, j);
            float ej = __shfl_sync(FULL, ex, j);
            if (act) {
                float2 hj = *(const float2*)(g_h + (size_t)sj * Do + 2 * lane);
                acc.x += ej * hj.x; acc.y += ej * hj.y;
            }
        }
    }
#pragma unroll
    for (int o = 16; o > 0; o >>= 1)
        den_p += __shfl_xor_sync(FULL, den_p, o);
    float inv = 1.f / den_p;

    if (MODE == 0) {
        float2 bv = *(const float2*)(b + 2 * lane);
        float2 o2;
        o2.x = fmaxf(acc.x * inv + bv.x, 0.f);
        o2.y = fmaxf(acc.y * inv + bv.y, 0.f);
        *(float2*)(out + (size_t)n * 64 + 2 * lane) = o2;
    } else {
        float v0 = act ? (acc.x * inv + b[2 * lane])     : -INFINITY;
        float v1 = act ? (acc.y * inv + b[2 * lane + 1]) : -INFINITY;
        float mx = fmaxf(v0, v1);
#pragma unroll
        for (int o = 16; o > 0; o >>= 1)
            mx = fmaxf(mx, __shfl_xor_sync(FULL, mx, o));
        float sum = act ? (expf(v0 - mx) + expf(v1 - mx)) : 0.f;
#pragma unroll
        for (int o = 16; o > 0; o >>= 1)
            sum += __shfl_xor_sync(FULL, sum, o);
        float ls = mx + logf(sum);
        if (act) {
            out[(size_t)n * 40 + 2 * lane]     = v0 - ls;
            out[(size_t)n * 40 + 2 * lane + 1] = v1 - ls;
        }
    }
}

extern "C" void kernel_launch(void* const* d_in, const int* in_sizes, int n_in,
                              void* d_out, int out_size) {
    const int N = in_sizes[0] / 64;
    const int E = in_sizes[1] / 2;
    const float* x  = (const float*)d_in[0];
    const int*   ei = (const int*)d_in[1];     // int32 (JAX downcasts int64)

    const int TB = 256;
    int e4blk = ((E + 3) / 4 + TB - 1) / TB;
    int sblk  = (N + SCAN_B - 1) / SCAN_B;
    int gemm_grid = (N + 63) / 64;
    int agg_grid  = (N + 7) / 8;

    // ---- CSR build (scatter_k also restores g_deg/g_flag zero-invariant) ----
    hist_k<<<e4blk, TB>>>(ei, E);
    scan_k<<<sblk, SCAN_B>>>(N);
    scatter_k<<<e4blk, TB>>>(ei, E, N);

    // ---------- layer 0 ----------
    gemm_attn<64, false><<<gemm_grid, TB>>>(x, (const float*)d_in[2],
                                            (const float*)d_in[3], (const float*)d_in[4], N);
    agg<64, 0, true><<<agg_grid, TB>>>((const float*)d_in[5], nullptr, N);

    // ---------- layer 1 ----------
    gemm_attn<64, true><<<gemm_grid, TB>>>(nullptr, (const float*)d_in[6],
                                           (const float*)d_in[7], (const float*)d_in[8], N);
    agg<64, 0, true><<<agg_grid, TB>>>((const float*)d_in[9], nullptr, N);

    // ---------- layer 2 ----------
    gemm_attn<40, true><<<gemm_grid, TB>>>(nullptr, (const float*)d_in[10],
                                           (const float*)d_in[11], (const float*)d_in[12], N);
    agg<40, 1, false><<<agg_grid, TB>>>((const float*)d_in[13], (float*)d_out, N);
}

// round 15
// speedup vs baseline: 1.0780x; 1.0707x over previous
#include <cuda_runtime.h>
#include <cuda_fp16.h>
#include <math.h>

#define MAXN 100000
#define MAXE 1200000
#define SCAN_B 512
#define MAXBLK 256

// ---- scratch (static __device__, allocation-free; zero-initialized at load) ----
__device__ __align__(16) float   g_h[(size_t)MAXN * 64];  // h = x@W (fp32, row stride Do)
__device__ __align__(16) __half2 g_hh[(size_t)MAXN * 32]; // h in fp16 (row stride Do/2)
__device__ float                 g_as[MAXN];              // h @ a_src
__device__ float                 g_ad[MAXN];              // h @ a_dst
__device__ __align__(16) float   g_x[(size_t)MAXN * 64];  // layer output -> next input
__device__ int                   g_deg[MAXN];             // in-degree (ZERO at call entry)
__device__ int                   g_rowptr[MAXN];          // after scatter: rowptr[n] = end(n)
__device__ int                   g_csrc[MAXE];            // CSR src indices (grouped by dst)
// decoupled-lookback scan state (ZERO flags at call entry)
__device__ volatile int          g_flag[MAXBLK];
__device__ volatile int          g_aggr[MAXBLK];
__device__ volatile int          g_incl[MAXBLK];

__device__ __forceinline__ float lrelu(float x) { return x > 0.f ? x : 0.2f * x; }

// ================= CSR build =================

__global__ void hist_k(const int* __restrict__ ei, int E) {
    int i4 = blockIdx.x * blockDim.x + threadIdx.x;
    const int* dst = ei + E;
    int base = i4 * 4;
    if (base + 3 < E) {
        int4 d = *(const int4*)(dst + base);
        atomicAdd(&g_deg[d.x], 1);
        atomicAdd(&g_deg[d.y], 1);
        atomicAdd(&g_deg[d.z], 1);
        atomicAdd(&g_deg[d.w], 1);
    } else {
        for (int i = base; i < E; i++) atomicAdd(&g_deg[dst[i]], 1);
    }
}

// single-pass exclusive scan (decoupled lookback); g_flag zero at entry
__global__ void scan_k(int N) {
    __shared__ int wsum[16];
    __shared__ int s_off;
    int tid = threadIdx.x, b = blockIdx.x;
    int lane = tid & 31, wid = tid >> 5;
    int i = b * SCAN_B + tid;
    int v = (i < N) ? g_deg[i] : 0;

    int x = v;
#pragma unroll
    for (int o = 1; o < 32; o <<= 1) {
        int t = __shfl_up_sync(0xffffffffu, x, o);
        if (lane >= o) x += t;
    }
    if (lane == 31) wsum[wid] = x;
    __syncthreads();
    if (wid == 0 && lane < 16) {
        int y = wsum[lane];
#pragma unroll
        for (int o = 1; o < 16; o <<= 1) {
            int t = __shfl_up_sync(0x0000ffffu, y, o);
            if (lane >= o) y += t;
        }
        wsum[lane] = y;
    }
    __syncthreads();
    int incl  = x + (wid > 0 ? wsum[wid - 1] : 0);
    int total = wsum[15];

    if (tid == 0) {
        if (b == 0) {
            g_incl[0] = total;
            __threadfence();
            g_flag[0] = 2;
            s_off = 0;
        } else {
            g_aggr[b] = total;
            __threadfence();
            g_flag[b] = 1;
            int run = 0;
            for (int p = b - 1; p >= 0; p--) {
                int f;
                do { f = g_flag[p]; } while (f == 0);
                if (f == 2) { run += g_incl[p]; break; }
                run += g_aggr[p];
            }
            s_off = run;
            g_incl[b] = run + total;
            __threadfence();
            g_flag[b] = 2;
        }
    }
    __syncthreads();
    if (i < N) g_rowptr[i] = s_off + incl - v;     // exclusive
}

__global__ void scatter_k(const int* __restrict__ ei, int E) {
    int i4 = blockIdx.x * blockDim.x + threadIdx.x;
    int base = i4 * 4;
    if (base + 3 < E) {
        int4 s = *(const int4*)(ei + base);
        int4 d = *(const int4*)(ei + E + base);
        g_csrc[atomicAdd(&g_rowptr[d.x], 1)] = s.x;
        g_csrc[atomicAdd(&g_rowptr[d.y], 1)] = s.y;
        g_csrc[atomicAdd(&g_rowptr[d.z], 1)] = s.z;
        g_csrc[atomicAdd(&g_rowptr[d.w], 1)] = s.w;
    } else {
        for (int i = base; i < E; i++)
            g_csrc[atomicAdd(&g_rowptr[ei[E + i]], 1)] = ei[i];
    }
}

// restore zeroed-state invariant for the next call (runs LAST)
__global__ void cleanup(int N) {
    int i = blockIdx.x * blockDim.x + threadIdx.x;
    if (i < N) g_deg[i] = 0;
    if (i < MAXBLK) g_flag[i] = 0;
}

// ================= K1: register-tiled GEMM + attention scores =================
// (R10 config — measured best.) 64x64 tile, 256 threads, 4x4 per thread.
// As[k][row] stride 68 (16B-aligned rows + bank rotation); Bs[k][col].
// Epilogue also writes fp16 copy g_hh for the aggregate's gathers.
template <int Do, bool FROMG>
__global__ void gemm_attn(const float* __restrict__ xin, const float* __restrict__ W,
                          const float* __restrict__ a_s, const float* __restrict__ a_d,
                          int N) {
    const int Din = 64;
    __shared__ float As[Din][68];
    __shared__ float Bs[Din][64];

    int t  = threadIdx.x;
    int tx = t & 15;
    int ty = t >> 4;
    int rowbase = blockIdx.x * 64;

    const float* src = FROMG ? g_x : xin;

    {
        int r0 = t >> 4;
        int k4 = (t & 15) * 4;
#pragma unroll
        for (int q = 0; q < 4; q++) {
            int r = r0 + q * 16;
            int row = rowbase + r;
            float4 x4 = (row < N) ? *(const float4*)(src + (size_t)row * Din + k4)
                                  : make_float4(0.f, 0.f, 0.f, 0.f);
            As[k4 + 0][r] = x4.x;
            As[k4 + 1][r] = x4.y;
            As[k4 + 2][r] = x4.z;
            As[k4 + 3][r] = x4.w;
        }
    }
    {
        int kk = t >> 4;
        int c4 = (t & 15) * 4;
#pragma unroll
        for (int q = 0; q < 4; q++) {
            int k = kk + q * 16;
            float4 w4 = (c4 < Do) ? *(const float4*)(W + (size_t)k * Do + c4)
                                  : make_float4(0.f, 0.f, 0.f, 0.f);
            *(float4*)&Bs[k][c4] = w4;
        }
    }
    __syncthreads();

    float acc[4][4] = {};
#pragma unroll 8
    for (int k = 0; k < Din; k++) {
        float4 a  = *(const float4*)&As[k][ty * 4];
        float4 bb = *(const float4*)&Bs[k][tx * 4];
        acc[0][0] += a.x * bb.x; acc[0][1] += a.x * bb.y; acc[0][2] += a.x * bb.z; acc[0][3] += a.x * bb.w;
        acc[1][0] += a.y * bb.x; acc[1][1] += a.y * bb.y; acc[1][2] += a.y * bb.z; acc[1][3] += a.y * bb.w;
        acc[2][0] += a.z * bb.x; acc[2][1] += a.z * bb.y; acc[2][2] += a.z * bb.z; acc[2][3] += a.z * bb.w;
        acc[3][0] += a.w * bb.x; acc[3][1] += a.w * bb.y; acc[3][2] += a.w * bb.z; acc[3][3] += a.w * bb.w;
    }

    int c4 = tx * 4;
    float4 av = (c4 < Do) ? *(const float4*)(a_s + c4) : make_float4(0.f, 0.f, 0.f, 0.f);
    float4 dv = (c4 < Do) ? *(const float4*)(a_d + c4) : make_float4(0.f, 0.f, 0.f, 0.f);

#pragma unroll
    for (int i = 0; i < 4; i++) {
        int row = rowbase + ty * 4 + i;
        float ps = acc[i][0] * av.x + acc[i][1] * av.y + acc[i][2] * av.z + acc[i][3] * av.w;
        float pd = acc[i][0] * dv.x + acc[i][1] * dv.y + acc[i][2] * dv.z + acc[i][3] * dv.w;
#pragma unroll
        for (int o = 8; o > 0; o >>= 1) {
            ps += __shfl_xor_sync(0xffffffffu, ps, o);
            pd += __shfl_xor_sync(0xffffffffu, pd, o);
        }
        if (row < N) {
            if (c4 < Do) {
                *(float4*)(g_h + (size_t)row * Do + c4) =
                    make_float4(acc[i][0], acc[i][1], acc[i][2], acc[i][3]);
                __half2* hp = g_hh + (size_t)row * (Do / 2) + tx * 2;
                hp[0] = __floats2half2_rn(acc[i][0], acc[i][1]);
                hp[1] = __floats2half2_rn(acc[i][2], acc[i][3]);
            }
            if (tx == 0) { g_as[row] = ps; g_ad[row] = pd; }
        }
    }
}

// ================= K2: softmax + aggregate (warp per node) ===================
// Scores/softmax/self in fp32; neighbor rows gathered in fp16 (g_hh, 4B/lane),
// accumulated in fp32. Shift by self-score (softmax shift-invariant).
// MODE 0: relu(acc/den + b) -> g_x (Do=64, GOUT=true); MODE 1: log_softmax -> out.
template <int Do, int MODE, bool GOUT>
__global__ void agg(const float* __restrict__ b, float* __restrict__ out_arg, int N) {
    const unsigned FULL = 0xffffffffu;
    const int HH = Do / 2;                   // half2 row stride
    float* out = GOUT ? g_x : out_arg;
    int w    = (blockIdx.x * blockDim.x + threadIdx.x) >> 5;
    int lane = threadIdx.x & 31;
    if (w >= N) return;
    const int n = w;

    int end   = g_rowptr[n];
    int start = end - g_deg[n];
    float ad_n  = g_ad[n];
    float eself = lrelu(g_as[n] + ad_n);

    bool act = (lane < HH);
    float2 acc = act ? *(const float2*)(g_h + (size_t)n * Do + 2 * lane)
                     : make_float2(0.f, 0.f);            // self contribution (ex=1, fp32)
    float den_p = (lane == 0) ? 1.f : 0.f;

    for (int base = start; base < end; base += 32) {
        int i = base + lane;
        int   s = 0;
        float ex = 0.f;
        if (i < end) {
            s  = g_csrc[i];
            ex = __expf(lrelu(g_as[s] + ad_n) - eself);
        }
        den_p += ex;

        int cnt = min(32, end - base);
        int j = 0;
        for (; j + 4 <= cnt; j += 4) {
            int   s0 = __shfl_sync(FULL, s, j),     s1 = __shfl_sync(FULL, s, j + 1);
            int   s2 = __shfl_sync(FULL, s, j + 2), s3 = __shfl_sync(FULL, s, j + 3);
            float e0 = __shfl_sync(FULL, ex, j),     e1 = __shfl_sync(FULL, ex, j + 1);
            float e2 = __shfl_sync(FULL, ex, j + 2), e3 = __shfl_sync(FULL, ex, j + 3);
            if (act) {
                float2 h0 = __half22float2(g_hh[(size_t)s0 * HH + lane]);
                float2 h1 = __half22float2(g_hh[(size_t)s1 * HH + lane]);
                float2 h2 = __half22float2(g_hh[(size_t)s2 * HH + lane]);
                float2 h3 = __half22float2(g_hh[(size_t)s3 * HH + lane]);
                acc.x += e0 * h0.x; acc.y += e0 * h0.y;
                acc.x += e1 * h1.x; acc.y += e1 * h1.y;
                acc.x += e2 * h2.x; acc.y += e2 * h2.y;
                acc.x += e3 * h3.x; acc.y += e3 * h3.y;
            }
        }
        for (; j < cnt; j++) {
            int   sj = __shfl_sync(FULL, s, j);
            float ej = __shfl_sync(FULL, ex, j);
            if (act) {
                float2 hj = __half22float2(g_hh[(size_t)sj * HH + lane]);
                acc.x += ej * hj.x; acc.y += ej * hj.y;
            }
        }
    }
#pragma unroll
    for (int o = 16; o > 0; o >>= 1)
        den_p += __shfl_xor_sync(FULL, den_p, o);
    float inv = 1.f / den_p;

    if (MODE == 0) {
        float2 bv = *(const float2*)(b + 2 * lane);
        float2 o2;
        o2.x = fmaxf(acc.x * inv + bv.x, 0.f);
        o2.y = fmaxf(acc.y * inv + bv.y, 0.f);
        *(float2*)(out + (size_t)n * 64 + 2 * lane) = o2;
    } else {
        float v0 = act ? (acc.x * inv + b[2 * lane])     : -INFINITY;
        float v1 = act ? (acc.y * inv + b[2 * lane + 1]) : -INFINITY;
        float mx = fmaxf(v0, v1);
#pragma unroll
        for (int o = 16; o > 0; o >>= 1)
            mx = fmaxf(mx, __shfl_xor_sync(FULL, mx, o));
        float sum = act ? (expf(v0 - mx) + expf(v1 - mx)) : 0.f;
#pragma unroll
        for (int o = 16; o > 0; o >>= 1)
            sum += __shfl_xor_sync(FULL, sum, o);
        float ls = mx + logf(sum);
        if (act) {
            out[(size_t)n * 40 + 2 * lane]     = v0 - ls;
            out[(size_t)n * 40 + 2 * lane + 1] = v1 - ls;
        }
    }
}

extern "C" void kernel_launch(void* const* d_in, const int* in_sizes, int n_in,
                              void* d_out, int out_size) {
    const int N = in_sizes[0] / 64;
    const int E = in_sizes[1] / 2;
    const float* x  = (const float*)d_in[0];
    const int*   ei = (const int*)d_in[1];     // int32 (JAX downcasts int64)

    const int TB = 256;
    int nblk  = (N + TB - 1) / TB;
    int e4blk = ((E + 3) / 4 + TB - 1) / TB;
    int sblk  = (N + SCAN_B - 1) / SCAN_B;
    int gemm_grid = (N + 63) / 64;
    int agg_grid  = (N + 7) / 8;

    // ---- CSR build ----
    hist_k<<<e4blk, TB>>>(ei, E);
    scan_k<<<sblk, SCAN_B>>>(N);
    scatter_k<<<e4blk, TB>>>(ei, E);

    // ---------- layer 0 ----------
    gemm_attn<64, false><<<gemm_grid, TB>>>(x, (const float*)d_in[2],
                                            (const float*)d_in[3], (const float*)d_in[4], N);
    agg<64, 0, true><<<agg_grid, TB>>>((const float*)d_in[5], nullptr, N);

    // ---------- layer 1 ----------
    gemm_attn<64, true><<<gemm_grid, TB>>>(nullptr, (const float*)d_in[6],
                                           (const float*)d_in[7], (const float*)d_in[8], N);
    agg<64, 0, true><<<agg_grid, TB>>>((const float*)d_in[9], nullptr, N);

    // ---------- layer 2 ----------
    gemm_attn<40, true><<<gemm_grid, TB>>>(nullptr, (const float*)d_in[10],
                                           (const float*)d_in[11], (const float*)d_in[12], N);
    agg<40, 1, false><<<agg_grid, TB>>>((const float*)d_in[13], (float*)d_out, N);

    // ---- restore zeroed-state invariant for next call ----
    cleanup<<<nblk, TB>>>(N);
}